// round 6
// baseline (speedup 1.0000x reference)
// R6: fp32x2 packed FMA (fma.rn.f32x2) in prep GEMM + attn logits;
// rank-1 -> 3 warps x 4-slot float4 broadcast; upd de-staged (weights via L1).
#include <cuda_runtime.h>

#define BB 64
#define KK 4096
#define DD 64
#define QQ 11
#define HH 128
#define NITER 3
#define CPB 8
#define NACC 768         // per-CTA partial record (704 U + 11 S + 22 A1 + 22 A2)

#define PREP_SMEM ((8192 + 8704) * 4)          // sW 64x128 + sX 64x136
#define ATTN_SMEM ((704 + 17408 + 3072 + 512) * 4)

typedef unsigned long long ull;

__device__ __forceinline__ ull pack2(float x, float y) {
    ull r; asm("mov.b64 %0,{%1,%2};" : "=l"(r) : "f"(x), "f"(y)); return r;
}
__device__ __forceinline__ ull fma2(ull a, ull b, ull c) {
    ull d; asm("fma.rn.f32x2 %0,%1,%2,%3;" : "=l"(d) : "l"(a), "l"(b), "l"(c)); return d;
}
__device__ __forceinline__ float2 unpk2(ull v) {
    float2 f; asm("mov.b64 {%0,%1},%2;" : "=f"(f.x), "=f"(f.y) : "l"(v)); return f;
}

// ---------------- scratch ----------------
__device__ __align__(16) float g_k[BB * KK * DD];
__device__ __align__(16) float g_v[BB * KK * DD];
__device__ __align__(16) float g_grid[BB * KK * 2];
__device__ __align__(16) float g_slots[BB * QQ * DD];
__device__ __align__(16) float g_q[BB * QQ * DD];
__device__ __align__(16) float g_part[BB * CPB * NACC];

__device__ __forceinline__ float bsum64(float v, volatile float* red) {
    #pragma unroll
    for (int o = 16; o; o >>= 1) v += __shfl_xor_sync(0xffffffffu, v, o);
    int t = threadIdx.x;
    if ((t & 31) == 0) red[t >> 5] = v;
    __syncthreads();
    float r = red[0] + red[1];
    __syncthreads();
    return r;
}
__device__ __forceinline__ float rowsum64(float v, int t, volatile float* red2) {
    #pragma unroll
    for (int o = 16; o; o >>= 1) v += __shfl_xor_sync(0xffffffffu, v, o);
    if ((t & 31) == 0) red2[t >> 5] = v;
    __syncthreads();
    float r = red2[0] + red2[1];
    __syncthreads();
    return r;
}

// ================= Kernel 1: PE + 2x LN + K/V projection (f32x2 GEMM) ==========
// grid: BB*32 CTAs (128 rows each), 256 threads
__global__ void __launch_bounds__(256) prep_kernel(
    const float* __restrict__ in, const float* __restrict__ Wpe, const float* __restrict__ bpe,
    const float* __restrict__ ges, const float* __restrict__ geb,
    const float* __restrict__ ins, const float* __restrict__ inb,
    const float* __restrict__ Wk, const float* __restrict__ Wv)
{
    extern __shared__ float dsm[];
    float* sW = dsm;              // [64 d][128 cols] 0..63 Wk, 64..127 Wv
    float* sX = dsm + 8192;       // [64 d][rows], stride 136

    int t = threadIdx.x;
    int bid = blockIdx.x;
    int b = bid >> 5;
    int row0 = (bid & 31) * 128;

    for (int i = t; i < 8192; i += 256) {
        int d = i >> 7, col = i & 127;
        sW[i] = (col < 64) ? Wk[d * 64 + col] : Wv[d * 64 + col - 64];
    }
    int lane = t & 31;
    int w = t >> 5;

    float pe00 = Wpe[lane],      pe01 = Wpe[32 + lane];
    float pe10 = Wpe[64 + lane], pe11 = Wpe[96 + lane];
    float bp0 = bpe[lane],  bp1 = bpe[32 + lane];
    float gs0 = ges[lane],  gs1 = ges[32 + lane];
    float gb0 = geb[lane],  gb1 = geb[32 + lane];
    float is0 = ins[lane],  is1 = ins[32 + lane];
    float ib0 = inb[lane],  ib1 = inb[32 + lane];

    // phase 1: LN pipeline, 8 warps x 16 rows, store x transposed into sX
    for (int r = 0; r < 16; ++r) {
        int lrow = w * 16 + r;
        int row = row0 + lrow;
        const float* src = in + (size_t)(b * KK + row) * 66;
        float f0 = src[lane], f1 = src[32 + lane];
        float gx = src[64], gy = src[65];
        float x0 = f0 + gx * pe00 + gy * pe10 + bp0;
        float x1 = f1 + gx * pe01 + gy * pe11 + bp1;

        float s = x0 + x1;
        #pragma unroll
        for (int o = 16; o; o >>= 1) s += __shfl_xor_sync(0xffffffffu, s, o);
        float m = s * (1.f / 64.f);
        float d0 = x0 - m, d1 = x1 - m;
        float vv = d0 * d0 + d1 * d1;
        #pragma unroll
        for (int o = 16; o; o >>= 1) vv += __shfl_xor_sync(0xffffffffu, vv, o);
        float inv = rsqrtf(vv * (1.f / 64.f) + 1e-6f);
        x0 = d0 * inv * gs0 + gb0;
        x1 = d1 * inv * gs1 + gb1;

        s = x0 + x1;
        #pragma unroll
        for (int o = 16; o; o >>= 1) s += __shfl_xor_sync(0xffffffffu, s, o);
        m = s * (1.f / 64.f);
        d0 = x0 - m; d1 = x1 - m;
        vv = d0 * d0 + d1 * d1;
        #pragma unroll
        for (int o = 16; o; o >>= 1) vv += __shfl_xor_sync(0xffffffffu, vv, o);
        inv = rsqrtf(vv * (1.f / 64.f) + 1e-6f);
        x0 = d0 * inv * is0 + ib0;
        x1 = d1 * inv * is1 + ib1;

        sX[lane * 136 + lrow]        = x0;
        sX[(lane + 32) * 136 + lrow] = x1;
        if (lane == 0) {
            g_grid[(b * KK + row) * 2]     = gx;
            g_grid[(b * KK + row) * 2 + 1] = gy;
        }
    }
    __syncthreads();

    // phase 2: GEMM [128 rows x 64 d] @ [64 d x 128 cols], 8 rows x 8 cols / thread
    int cg = t & 15, rg = t >> 4;
    int c0 = cg * 8, r0 = rg * 8;
    ull acc2[8][4];
    #pragma unroll
    for (int i = 0; i < 8; i++)
        #pragma unroll
        for (int j = 0; j < 4; j++) acc2[i][j] = 0ull;

    #pragma unroll 2
    for (int d = 0; d < 64; ++d) {
        const float* xr = sX + d * 136 + r0;
        float4 xa = *(const float4*)xr;
        float4 xb = *(const float4*)(xr + 4);
        ull xp[8];
        xp[0] = pack2(xa.x, xa.x); xp[1] = pack2(xa.y, xa.y);
        xp[2] = pack2(xa.z, xa.z); xp[3] = pack2(xa.w, xa.w);
        xp[4] = pack2(xb.x, xb.x); xp[5] = pack2(xb.y, xb.y);
        xp[6] = pack2(xb.z, xb.z); xp[7] = pack2(xb.w, xb.w);
        ulonglong2 wa = *(const ulonglong2*)(sW + d * 128 + c0);
        ulonglong2 wb = *(const ulonglong2*)(sW + d * 128 + c0 + 4);
        #pragma unroll
        for (int i = 0; i < 8; i++) {
            acc2[i][0] = fma2(xp[i], wa.x, acc2[i][0]);
            acc2[i][1] = fma2(xp[i], wa.y, acc2[i][1]);
            acc2[i][2] = fma2(xp[i], wb.x, acc2[i][2]);
            acc2[i][3] = fma2(xp[i], wb.y, acc2[i][3]);
        }
    }

    size_t gbase = (size_t)(b * KK + row0 + r0) * 64;
    #pragma unroll
    for (int i = 0; i < 8; i++) {
        float2 p0 = unpk2(acc2[i][0]), p1 = unpk2(acc2[i][1]);
        float2 p2 = unpk2(acc2[i][2]), p3 = unpk2(acc2[i][3]);
        float4 va = make_float4(p0.x, p0.y, p1.x, p1.y);
        float4 vb = make_float4(p2.x, p2.y, p3.x, p3.y);
        size_t off = gbase + (size_t)i * 64;
        if (cg < 8) {
            *(float4*)(g_k + off + c0)     = va;
            *(float4*)(g_k + off + c0 + 4) = vb;
        } else {
            *(float4*)(g_v + off + c0 - 64) = va;
            *(float4*)(g_v + off + c0 - 60) = vb;
        }
    }
}

// ================= Kernel 2: iter-0 q projection =================
__global__ void __launch_bounds__(64) q_kernel(
    const float* __restrict__ slots_in, const float* __restrict__ qs,
    const float* __restrict__ qb, const float* __restrict__ Wq)
{
    __shared__ float xs[64];
    __shared__ float red[2];
    int row = blockIdx.x, t = threadIdx.x;
    float sv = slots_in[row * 68 + t];
    g_slots[row * 64 + t] = sv;
    float m = bsum64(sv, red) * (1.f / 64.f);
    float dv = sv - m;
    float var = bsum64(dv * dv, red) * (1.f / 64.f);
    float xn = dv * rsqrtf(var + 1e-6f) * qs[t] + qb[t];
    xs[t] = xn;
    __syncthreads();
    float acc = 0.f;
    #pragma unroll
    for (int d = 0; d < 64; ++d) acc += xs[d] * Wq[d * 64 + t];
    g_q[row * 64 + t] = acc * 0.125f;
}

// ================= Kernel 3: streaming attention ================================
// grid: B*CPB = 512 CTAs, 128 threads, 2 keys/thread, 2 tiles of 256 keys.
__global__ void __launch_bounds__(128) attn_kernel(int last)
{
    extern __shared__ float dsm[];
    float* sQ  = dsm;                        // 704
    float* sKV = dsm + 704;                  // 256*68
    float* sA  = dsm + 704 + 17408;          // 256*12 (stride 12, q11 pad=0)
    float* sG  = dsm + 704 + 17408 + 3072;   // 512

    int t = threadIdx.x;
    int b = blockIdx.x >> 3, c = blockIdx.x & 7;
    int key0 = c * 512;

    for (int i = t; i < 704; i += 128) sQ[i] = g_q[b * 704 + i];

    int dg = t & 31, qw = t >> 5;

    float aU[4][2] = {{0,0},{0,0},{0,0},{0,0}};
    float sS[11];
    float a1x[11], a1y[11], a2x[11], a2y[11];
    #pragma unroll
    for (int i = 0; i < 11; i++) { sS[i]=0.f; a1x[i]=0.f; a1y[i]=0.f; a2x[i]=0.f; a2y[i]=0.f; }

    for (int tile = 0; tile < 2; ++tile) {
        int kb = key0 + tile * 256;
        __syncthreads();
        const float4* gk = (const float4*)(g_k + ((size_t)b * KK + kb) * 64);
        for (int i = t; i < 4096; i += 128)
            *((float4*)(sKV + (i >> 4) * 68) + (i & 15)) = gk[i];
        const float4* gg = (const float4*)(g_grid + ((size_t)b * KK + kb) * 2);
        for (int i = t; i < 128; i += 128) ((float4*)sG)[i] = gg[i];
        __syncthreads();

        // logits for keys t and t+128 (f32x2 over d-pairs)
        ull lp0[11], lp1[11];
        #pragma unroll
        for (int i = 0; i < 11; i++) { lp0[i] = 0ull; lp1[i] = 0ull; }
        #pragma unroll 2
        for (int d4 = 0; d4 < 16; ++d4) {
            ulonglong2 k0 = *(const ulonglong2*)(sKV + t * 68 + d4 * 4);
            ulonglong2 k1 = *(const ulonglong2*)(sKV + (t + 128) * 68 + d4 * 4);
            #pragma unroll
            for (int qi = 0; qi < 11; qi++) {
                ulonglong2 qv = *(const ulonglong2*)(sQ + qi * 64 + d4 * 4);
                lp0[qi] = fma2(qv.x, k0.x, lp0[qi]);
                lp0[qi] = fma2(qv.y, k0.y, lp0[qi]);
                lp1[qi] = fma2(qv.x, k1.x, lp1[qi]);
                lp1[qi] = fma2(qv.y, k1.y, lp1[qi]);
            }
        }
        float l0[11], l1[11];
        #pragma unroll
        for (int i = 0; i < 11; i++) {
            float2 u0 = unpk2(lp0[i]); l0[i] = u0.x + u0.y;
            float2 u1 = unpk2(lp1[i]); l1[i] = u1.x + u1.y;
        }
        float mx0 = l0[0], mx1 = l1[0];
        #pragma unroll
        for (int i = 1; i < 11; i++) { mx0 = fmaxf(mx0, l0[i]); mx1 = fmaxf(mx1, l1[i]); }
        float sum0 = 0.f, sum1 = 0.f;
        #pragma unroll
        for (int i = 0; i < 11; i++) {
            l0[i] = __expf(l0[i] - mx0); sum0 += l0[i];
            l1[i] = __expf(l1[i] - mx1); sum1 += l1[i];
        }
        float inv0 = 1.f / sum0, inv1 = 1.f / sum1;
        float gx0 = sG[2 * t], gy0 = sG[2 * t + 1];
        float gx1 = sG[2 * (t + 128)], gy1 = sG[2 * (t + 128) + 1];
        float gxx0 = gx0 * gx0, gyy0 = gy0 * gy0;
        float gxx1 = gx1 * gx1, gyy1 = gy1 * gy1;
        #pragma unroll
        for (int i = 0; i < 11; i++) {
            float a0 = l0[i] * inv0;
            float a1 = l1[i] * inv1;
            sA[t * 12 + i]         = a0;
            sA[(t + 128) * 12 + i] = a1;
            sS[i] += a0 + a1;
            if (last) {
                a1x[i] += a0 * gx0 + a1 * gx1;
                a1y[i] += a0 * gy0 + a1 * gy1;
                a2x[i] += a0 * gxx0 + a1 * gxx1;
                a2y[i] += a0 * gyy0 + a1 * gyy1;
            }
        }
        sA[t * 12 + 11] = 0.f;
        sA[(t + 128) * 12 + 11] = 0.f;
        __syncthreads();

        const float4* gv = (const float4*)(g_v + ((size_t)b * KK + kb) * 64);
        for (int i = t; i < 4096; i += 128)
            *((float4*)(sKV + (i >> 4) * 68) + (i & 15)) = gv[i];
        __syncthreads();

        // rank-1: warps 0-2 handle 4 slots each (q11 is zero pad)
        if (qw < 3) {
            #pragma unroll 4
            for (int key = 0; key < 256; ++key) {
                float4 a4 = *(const float4*)(sA + key * 12 + qw * 4);   // broadcast
                float v0 = sKV[key * 68 + dg];
                float v1 = sKV[key * 68 + dg + 32];
                aU[0][0] += a4.x * v0; aU[0][1] += a4.x * v1;
                aU[1][0] += a4.y * v0; aU[1][1] += a4.y * v1;
                aU[2][0] += a4.z * v0; aU[2][1] += a4.z * v1;
                aU[3][0] += a4.w * v0; aU[3][1] += a4.w * v1;
            }
        }
    }

    __syncthreads();
    float* red = sKV;
    size_t base = ((size_t)b * CPB + c) * NACC;
    if (qw < 3) {
        #pragma unroll
        for (int i = 0; i < 4; i++) {
            int q = qw * 4 + i;
            if (q < 11) {
                g_part[base + q * 64 + dg]      = aU[i][0];
                g_part[base + q * 64 + dg + 32] = aU[i][1];
            }
        }
    }
    int w = t >> 5, lane = t & 31;
    #define RED1(v, slot) { float _x = (v); \
        _Pragma("unroll") for (int _o = 16; _o; _o >>= 1) _x += __shfl_xor_sync(0xffffffffu, _x, _o); \
        if (lane == 0) red[w * 64 + (slot)] = _x; }
    #pragma unroll
    for (int i = 0; i < 11; i++) RED1(sS[i], i);
    if (last) {
        #pragma unroll
        for (int i = 0; i < 11; i++) {
            RED1(a1x[i], 11 + i); RED1(a1y[i], 22 + i);
            RED1(a2x[i], 33 + i); RED1(a2y[i], 44 + i);
        }
    }
    #undef RED1
    __syncthreads();
    int nvals = last ? 55 : 11;
    if (t < nvals) {
        float tot = red[t] + red[64 + t] + red[128 + t] + red[192 + t];
        int off;
        if (t < 11)      off = 704 + t;
        else if (t < 22) off = 715 + (t - 11) * 2;
        else if (t < 33) off = 716 + (t - 22) * 2;
        else if (t < 44) off = 737 + (t - 33) * 2;
        else             off = 738 + (t - 44) * 2;
        g_part[base + off] = tot;
    }
}

// ================= Kernel 4: GRU + MLP update (weights via L1) ==================
// grid: 88 blocks x 512 threads, 8 rows/block
__global__ void __launch_bounds__(512) upd_kernel(
    const float* __restrict__ Wir, const float* __restrict__ Wiz, const float* __restrict__ Win,
    const float* __restrict__ bir, const float* __restrict__ biz, const float* __restrict__ binp,
    const float* __restrict__ Whr, const float* __restrict__ Whz, const float* __restrict__ Whn,
    const float* __restrict__ bhn, const float* __restrict__ mls, const float* __restrict__ mlb,
    const float* __restrict__ W1, const float* __restrict__ b1,
    const float* __restrict__ W2, const float* __restrict__ b2,
    const float* __restrict__ Wq, const float* __restrict__ qs, const float* __restrict__ qb,
    float* __restrict__ outp, int last)
{
    __shared__ float s_upd[8][64], s_sl[8][64], s_xn[8][64], s_hb[8][128];
    __shared__ float s_red[8][2];

    int tid = threadIdx.x;
    int r = tid >> 6, t = tid & 63;
    int bq = blockIdx.x * 8 + r;
    int b = bq / 11, q = bq - b * 11;
    const float* pb = g_part + (size_t)b * CPB * NACC;

    float U = 0.f, S = 0.f;
    #pragma unroll
    for (int cc = 0; cc < CPB; cc++) {
        U += pb[cc * NACC + q * 64 + t];
        S += pb[cc * NACC + 704 + q];
    }
    float u = U / (S + 1e-8f);
    s_upd[r][t] = u;
    float slv = g_slots[bq * 64 + t];
    s_sl[r][t] = slv;
    __syncthreads();

    float air = bir[t], aiz = biz[t], ain = binp[t];
    float ahr = 0.f, ahz = 0.f, ahn = bhn[t];
    #pragma unroll 4
    for (int d = 0; d < 64; ++d) {
        float ud = s_upd[r][d], sd = s_sl[r][d];
        air += ud * Wir[d * 64 + t];
        aiz += ud * Wiz[d * 64 + t];
        ain += ud * Win[d * 64 + t];
        ahr += sd * Whr[d * 64 + t];
        ahz += sd * Whz[d * 64 + t];
        ahn += sd * Whn[d * 64 + t];
    }
    float rg = 1.f / (1.f + __expf(-(air + ahr)));
    float zg = 1.f / (1.f + __expf(-(aiz + ahz)));
    float ng = tanhf(ain + rg * ahn);
    float snew = (1.f - zg) * ng + zg * slv;

    float m = rowsum64(snew, t, s_red[r]) * (1.f / 64.f);
    float dv = snew - m;
    float var = rowsum64(dv * dv, t, s_red[r]) * (1.f / 64.f);
    float x = dv * rsqrtf(var + 1e-6f) * mls[t] + mlb[t];
    s_xn[r][t] = x;
    __syncthreads();
    float h0 = b1[t], h1 = b1[64 + t];
    #pragma unroll 4
    for (int d = 0; d < 64; ++d) {
        float xd = s_xn[r][d];
        h0 += xd * W1[d * 128 + t];
        h1 += xd * W1[d * 128 + 64 + t];
    }
    s_hb[r][t] = fmaxf(h0, 0.f);
    s_hb[r][64 + t] = fmaxf(h1, 0.f);
    __syncthreads();
    float od = snew + b2[t];
    #pragma unroll 4
    for (int hh = 0; hh < 128; ++hh) od += s_hb[r][hh] * W2[hh * 64 + t];

    if (!last) {
        g_slots[bq * 64 + t] = od;
        float qm = rowsum64(od, t, s_red[r]) * (1.f / 64.f);
        float qd = od - qm;
        float qvar = rowsum64(qd * qd, t, s_red[r]) * (1.f / 64.f);
        float xq = qd * rsqrtf(qvar + 1e-6f) * qs[t] + qb[t];
        s_xn[r][t] = xq;
        __syncthreads();
        float acc = 0.f;
        #pragma unroll 4
        for (int d = 0; d < 64; ++d) acc += s_xn[r][d] * Wq[d * 64 + t];
        g_q[bq * 64 + t] = acc * 0.125f;
        return;
    }

    outp[bq * 68 + t] = od;
    float s1x = 0.f, s1y = 0.f, s2x = 0.f, s2y = 0.f;
    const float2* gg = (const float2*)(g_grid + (size_t)b * KK * 2);
    for (int k = t; k < KK; k += 64) {
        float2 g = gg[k];
        s1x += g.x; s1y += g.y; s2x += g.x * g.x; s2y += g.y * g.y;
    }
    s1x = rowsum64(s1x, t, s_red[r]); s1y = rowsum64(s1y, t, s_red[r]);
    s2x = rowsum64(s2x, t, s_red[r]); s2y = rowsum64(s2y, t, s_red[r]);
    if (t == 0) {
        float A1xv = 0.f, A1yv = 0.f, A2xv = 0.f, A2yv = 0.f;
        #pragma unroll
        for (int cc = 0; cc < CPB; cc++) {
            A1xv += pb[cc * NACC + 715 + q * 2];
            A1yv += pb[cc * NACC + 716 + q * 2];
            A2xv += pb[cc * NACC + 737 + q * 2];
            A2yv += pb[cc * NACC + 738 + q * 2];
        }
        float inv = 1.f / (S + 1e-8f);
        float px = A1xv * inv, py = A1yv * inv;
        float T = S * inv;
        float vx = A2xv * inv - px * px * (2.f - T)
                 + 1e-8f * (s2x - 2.f * px * s1x + 4096.f * px * px);
        float vy = A2yv * inv - py * py * (2.f - T)
                 + 1e-8f * (s2y - 2.f * py * s1y + 4096.f * py * py);
        float scx = fminf(fmaxf(sqrtf(fmaxf(vx, 0.f)), 0.01f), 5.f);
        float scy = fminf(fmaxf(sqrtf(fmaxf(vy, 0.f)), 0.01f), 5.f);
        outp[bq * 68 + 64] = px;
        outp[bq * 68 + 65] = py;
        outp[bq * 68 + 66] = scx;
        outp[bq * 68 + 67] = scy;
    }
}

// ================= launch =================
extern "C" void kernel_launch(void* const* d_in, const int* in_sizes, int n_in,
                              void* d_out, int out_size)
{
    (void)in_sizes; (void)n_in; (void)out_size;
    const float* slots  = (const float*)d_in[0];
    const float* inputs = (const float*)d_in[1];
    const float* Wpe  = (const float*)d_in[2];
    const float* bpe  = (const float*)d_in[3];
    const float* ges  = (const float*)d_in[4];
    const float* geb  = (const float*)d_in[5];
    const float* ins  = (const float*)d_in[6];
    const float* inb  = (const float*)d_in[7];
    const float* Wk   = (const float*)d_in[8];
    const float* Wv   = (const float*)d_in[9];
    const float* qs   = (const float*)d_in[10];
    const float* qb   = (const float*)d_in[11];
    const float* Wq   = (const float*)d_in[12];
    const float* Wir  = (const float*)d_in[13];
    const float* Wiz  = (const float*)d_in[14];
    const float* Win  = (const float*)d_in[15];
    const float* bir  = (const float*)d_in[16];
    const float* biz  = (const float*)d_in[17];
    const float* binp = (const float*)d_in[18];
    const float* Whr  = (const float*)d_in[19];
    const float* Whz  = (const float*)d_in[20];
    const float* Whn  = (const float*)d_in[21];
    const float* bhn  = (const float*)d_in[22];
    const float* mls  = (const float*)d_in[23];
    const float* mlb  = (const float*)d_in[24];
    const float* W1   = (const float*)d_in[25];
    const float* b1   = (const float*)d_in[26];
    const float* W2   = (const float*)d_in[27];
    const float* b2   = (const float*)d_in[28];
    float* out = (float*)d_out;

    cudaFuncSetAttribute(prep_kernel, cudaFuncAttributeMaxDynamicSharedMemorySize, PREP_SMEM);
    cudaFuncSetAttribute(attn_kernel, cudaFuncAttributeMaxDynamicSharedMemorySize, ATTN_SMEM);

    prep_kernel<<<BB * 32, 256, PREP_SMEM>>>(inputs, Wpe, bpe, ges, geb, ins, inb, Wk, Wv);
    q_kernel<<<BB * QQ, 64>>>(slots, qs, qb, Wq);
    for (int it = 0; it < NITER; ++it) {
        int last = (it == NITER - 1);
        attn_kernel<<<BB * CPB, 128, ATTN_SMEM>>>(last);
        upd_kernel<<<BB * QQ / 8, 512>>>(Wir, Wiz, Win, bir, biz, binp,
                                         Whr, Whz, Whn, bhn, mls, mlb,
                                         W1, b1, W2, b2, Wq, qs, qb, out, last);
    }
}

// round 7
// speedup vs baseline: 1.5231x; 1.5231x over previous
// R7: revert upd to R5 smem-staged (R6 de-staging regressed 24.8->68.4us);
// K/V stored fp16 (compute stays fp32); gstats split shifts ncu onto attn.
#include <cuda_runtime.h>
#include <cuda_fp16.h>

#define BB 64
#define KK 4096
#define DD 64
#define QQ 11
#define HH 128
#define NITER 3
#define CPB 8
#define NACC 768         // per-CTA partial record (704 U + 11 S + 22 A1 + 22 A2)

#define PREP_SMEM ((8192 + 8704) * 4)          // sW 64x128 + sX 64x136
#define ATTN_SMEM ((704 + 17408 + 3072 + 512) * 4)
#define UPD_SMEM  (45056 * 4)   // 6x4096 GRU + W1 8192 + W2 8192 + Wq 4096

typedef unsigned long long ull;

__device__ __forceinline__ ull pack2(float x, float y) {
    ull r; asm("mov.b64 %0,{%1,%2};" : "=l"(r) : "f"(x), "f"(y)); return r;
}
__device__ __forceinline__ ull fma2(ull a, ull b, ull c) {
    ull d; asm("fma.rn.f32x2 %0,%1,%2,%3;" : "=l"(d) : "l"(a), "l"(b), "l"(c)); return d;
}
__device__ __forceinline__ float2 unpk2(ull v) {
    float2 f; asm("mov.b64 {%0,%1},%2;" : "=f"(f.x), "=f"(f.y) : "l"(v)); return f;
}

// ---------------- scratch ----------------
__device__ __align__(16) __half g_kh[BB * KK * DD];   // 32 MB
__device__ __align__(16) __half g_vh[BB * KK * DD];   // 32 MB
__device__ __align__(16) float g_grid[BB * KK * 2];
__device__ __align__(16) float g_slots[BB * QQ * DD];
__device__ __align__(16) float g_q[BB * QQ * DD];
__device__ __align__(16) float g_part[BB * CPB * NACC];
__device__ __align__(16) float g_gm[BB * 4];          // per-batch sum g, sum g^2

__device__ __forceinline__ float bsum64(float v, volatile float* red) {
    #pragma unroll
    for (int o = 16; o; o >>= 1) v += __shfl_xor_sync(0xffffffffu, v, o);
    int t = threadIdx.x;
    if ((t & 31) == 0) red[t >> 5] = v;
    __syncthreads();
    float r = red[0] + red[1];
    __syncthreads();
    return r;
}
__device__ __forceinline__ float rowsum64(float v, int t, volatile float* red2) {
    #pragma unroll
    for (int o = 16; o; o >>= 1) v += __shfl_xor_sync(0xffffffffu, v, o);
    if ((t & 31) == 0) red2[t >> 5] = v;
    __syncthreads();
    float r = red2[0] + red2[1];
    __syncthreads();
    return r;
}

// ================= Kernel 1: PE + 2x LN + K/V projection (f32x2 GEMM) ==========
// grid: BB*32 CTAs (128 rows each), 256 threads
__global__ void __launch_bounds__(256) prep_kernel(
    const float* __restrict__ in, const float* __restrict__ Wpe, const float* __restrict__ bpe,
    const float* __restrict__ ges, const float* __restrict__ geb,
    const float* __restrict__ ins, const float* __restrict__ inb,
    const float* __restrict__ Wk, const float* __restrict__ Wv)
{
    extern __shared__ float dsm[];
    float* sW = dsm;              // [64 d][128 cols] 0..63 Wk, 64..127 Wv
    float* sX = dsm + 8192;       // [64 d][rows], stride 136

    int t = threadIdx.x;
    int bid = blockIdx.x;
    int b = bid >> 5;
    int row0 = (bid & 31) * 128;

    for (int i = t; i < 8192; i += 256) {
        int d = i >> 7, col = i & 127;
        sW[i] = (col < 64) ? Wk[d * 64 + col] : Wv[d * 64 + col - 64];
    }
    int lane = t & 31;
    int w = t >> 5;

    float pe00 = Wpe[lane],      pe01 = Wpe[32 + lane];
    float pe10 = Wpe[64 + lane], pe11 = Wpe[96 + lane];
    float bp0 = bpe[lane],  bp1 = bpe[32 + lane];
    float gs0 = ges[lane],  gs1 = ges[32 + lane];
    float gb0 = geb[lane],  gb1 = geb[32 + lane];
    float is0 = ins[lane],  is1 = ins[32 + lane];
    float ib0 = inb[lane],  ib1 = inb[32 + lane];

    for (int r = 0; r < 16; ++r) {
        int lrow = w * 16 + r;
        int row = row0 + lrow;
        const float* src = in + (size_t)(b * KK + row) * 66;
        float f0 = src[lane], f1 = src[32 + lane];
        float gx = src[64], gy = src[65];
        float x0 = f0 + gx * pe00 + gy * pe10 + bp0;
        float x1 = f1 + gx * pe01 + gy * pe11 + bp1;

        float s = x0 + x1;
        #pragma unroll
        for (int o = 16; o; o >>= 1) s += __shfl_xor_sync(0xffffffffu, s, o);
        float m = s * (1.f / 64.f);
        float d0 = x0 - m, d1 = x1 - m;
        float vv = d0 * d0 + d1 * d1;
        #pragma unroll
        for (int o = 16; o; o >>= 1) vv += __shfl_xor_sync(0xffffffffu, vv, o);
        float inv = rsqrtf(vv * (1.f / 64.f) + 1e-6f);
        x0 = d0 * inv * gs0 + gb0;
        x1 = d1 * inv * gs1 + gb1;

        s = x0 + x1;
        #pragma unroll
        for (int o = 16; o; o >>= 1) s += __shfl_xor_sync(0xffffffffu, s, o);
        m = s * (1.f / 64.f);
        d0 = x0 - m; d1 = x1 - m;
        vv = d0 * d0 + d1 * d1;
        #pragma unroll
        for (int o = 16; o; o >>= 1) vv += __shfl_xor_sync(0xffffffffu, vv, o);
        inv = rsqrtf(vv * (1.f / 64.f) + 1e-6f);
        x0 = d0 * inv * is0 + ib0;
        x1 = d1 * inv * is1 + ib1;

        sX[lane * 136 + lrow]        = x0;
        sX[(lane + 32) * 136 + lrow] = x1;
        if (lane == 0) {
            g_grid[(b * KK + row) * 2]     = gx;
            g_grid[(b * KK + row) * 2 + 1] = gy;
        }
    }
    __syncthreads();

    // GEMM [128 rows x 64 d] @ [64 d x 128 cols], 8 rows x 8 cols / thread (f32x2)
    int cg = t & 15, rg = t >> 4;
    int c0 = cg * 8, r0 = rg * 8;
    ull acc2[8][4];
    #pragma unroll
    for (int i = 0; i < 8; i++)
        #pragma unroll
        for (int j = 0; j < 4; j++) acc2[i][j] = 0ull;

    #pragma unroll 2
    for (int d = 0; d < 64; ++d) {
        const float* xr = sX + d * 136 + r0;
        float4 xa = *(const float4*)xr;
        float4 xb = *(const float4*)(xr + 4);
        ull xp[8];
        xp[0] = pack2(xa.x, xa.x); xp[1] = pack2(xa.y, xa.y);
        xp[2] = pack2(xa.z, xa.z); xp[3] = pack2(xa.w, xa.w);
        xp[4] = pack2(xb.x, xb.x); xp[5] = pack2(xb.y, xb.y);
        xp[6] = pack2(xb.z, xb.z); xp[7] = pack2(xb.w, xb.w);
        ulonglong2 wa = *(const ulonglong2*)(sW + d * 128 + c0);
        ulonglong2 wb = *(const ulonglong2*)(sW + d * 128 + c0 + 4);
        #pragma unroll
        for (int i = 0; i < 8; i++) {
            acc2[i][0] = fma2(xp[i], wa.x, acc2[i][0]);
            acc2[i][1] = fma2(xp[i], wa.y, acc2[i][1]);
            acc2[i][2] = fma2(xp[i], wb.x, acc2[i][2]);
            acc2[i][3] = fma2(xp[i], wb.y, acc2[i][3]);
        }
    }

    size_t gbase = (size_t)(b * KK + row0 + r0) * 64;
    #pragma unroll
    for (int i = 0; i < 8; i++) {
        float2 p0 = unpk2(acc2[i][0]), p1 = unpk2(acc2[i][1]);
        float2 p2 = unpk2(acc2[i][2]), p3 = unpk2(acc2[i][3]);
        __half2 h0 = __floats2half2_rn(p0.x, p0.y);
        __half2 h1 = __floats2half2_rn(p1.x, p1.y);
        __half2 h2 = __floats2half2_rn(p2.x, p2.y);
        __half2 h3 = __floats2half2_rn(p3.x, p3.y);
        uint4 pk;
        pk.x = *(unsigned*)&h0; pk.y = *(unsigned*)&h1;
        pk.z = *(unsigned*)&h2; pk.w = *(unsigned*)&h3;
        size_t off = gbase + (size_t)i * 64;
        if (cg < 8) *(uint4*)(g_kh + off + c0)      = pk;
        else        *(uint4*)(g_vh + off + c0 - 64) = pk;
    }
}

// ================= gstats: per-batch grid moments (also shifts ncu onto attn) ===
__global__ void __launch_bounds__(256) gstats_kernel()
{
    __shared__ float4 sred[8];
    int b = blockIdx.x, t = threadIdx.x;
    float s1x = 0.f, s1y = 0.f, s2x = 0.f, s2y = 0.f;
    const float2* gg = (const float2*)(g_grid + (size_t)b * KK * 2);
    for (int k = t; k < KK; k += 256) {
        float2 g = gg[k];
        s1x += g.x; s1y += g.y; s2x += g.x * g.x; s2y += g.y * g.y;
    }
    #pragma unroll
    for (int o = 16; o; o >>= 1) {
        s1x += __shfl_xor_sync(0xffffffffu, s1x, o);
        s1y += __shfl_xor_sync(0xffffffffu, s1y, o);
        s2x += __shfl_xor_sync(0xffffffffu, s2x, o);
        s2y += __shfl_xor_sync(0xffffffffu, s2y, o);
    }
    if ((t & 31) == 0) sred[t >> 5] = make_float4(s1x, s1y, s2x, s2y);
    __syncthreads();
    if (t == 0) {
        float4 a = sred[0];
        #pragma unroll
        for (int i = 1; i < 8; i++) {
            a.x += sred[i].x; a.y += sred[i].y; a.z += sred[i].z; a.w += sred[i].w;
        }
        *(float4*)(g_gm + b * 4) = a;
    }
}

// ================= iter-0 q projection =================
__global__ void __launch_bounds__(64) q_kernel(
    const float* __restrict__ slots_in, const float* __restrict__ qs,
    const float* __restrict__ qb, const float* __restrict__ Wq)
{
    __shared__ float xs[64];
    __shared__ float red[2];
    int row = blockIdx.x, t = threadIdx.x;
    float sv = slots_in[row * 68 + t];
    g_slots[row * 64 + t] = sv;
    float m = bsum64(sv, red) * (1.f / 64.f);
    float dv = sv - m;
    float var = bsum64(dv * dv, red) * (1.f / 64.f);
    float xn = dv * rsqrtf(var + 1e-6f) * qs[t] + qb[t];
    xs[t] = xn;
    __syncthreads();
    float acc = 0.f;
    #pragma unroll
    for (int d = 0; d < 64; ++d) acc += xs[d] * Wq[d * 64 + t];
    g_q[row * 64 + t] = acc * 0.125f;
}

// ================= attention: 512 CTAs, 128 threads, 2 tiles of 256 keys =======
__global__ void __launch_bounds__(128) attn_kernel(int last)
{
    extern __shared__ float dsm[];
    float* sQ  = dsm;                        // 704
    float* sKV = dsm + 704;                  // 256*68 (fp32, converted from half)
    float* sA  = dsm + 704 + 17408;          // 256*12
    float* sG  = dsm + 704 + 17408 + 3072;   // 512

    int t = threadIdx.x;
    int b = blockIdx.x >> 3, c = blockIdx.x & 7;
    int key0 = c * 512;

    for (int i = t; i < 704; i += 128) sQ[i] = g_q[b * 704 + i];

    int dg = t & 31, qw = t >> 5;

    float aU[4][2] = {{0,0},{0,0},{0,0},{0,0}};
    float sS[11];
    float a1x[11], a1y[11], a2x[11], a2y[11];
    #pragma unroll
    for (int i = 0; i < 11; i++) { sS[i]=0.f; a1x[i]=0.f; a1y[i]=0.f; a2x[i]=0.f; a2y[i]=0.f; }

    for (int tile = 0; tile < 2; ++tile) {
        int kb = key0 + tile * 256;
        __syncthreads();
        // K tile: 256 rows x 64 halves = 2048 uint4, convert to fp32 smem
        const uint4* gk = (const uint4*)(g_kh + ((size_t)b * KK + kb) * 64);
        for (int i = t; i < 2048; i += 128) {
            uint4 hv = gk[i];
            int row = i >> 3, cc = (i & 7) * 8;
            float2 f0 = __half22float2(*(__half2*)&hv.x);
            float2 f1 = __half22float2(*(__half2*)&hv.y);
            float2 f2 = __half22float2(*(__half2*)&hv.z);
            float2 f3 = __half22float2(*(__half2*)&hv.w);
            float* dst = sKV + row * 68 + cc;
            *(float4*)dst       = make_float4(f0.x, f0.y, f1.x, f1.y);
            *(float4*)(dst + 4) = make_float4(f2.x, f2.y, f3.x, f3.y);
        }
        const float4* gg = (const float4*)(g_grid + ((size_t)b * KK + kb) * 2);
        for (int i = t; i < 128; i += 128) ((float4*)sG)[i] = gg[i];
        __syncthreads();

        // logits for keys t and t+128 (f32x2 over d-pairs)
        ull lp0[11], lp1[11];
        #pragma unroll
        for (int i = 0; i < 11; i++) { lp0[i] = 0ull; lp1[i] = 0ull; }
        #pragma unroll 2
        for (int d4 = 0; d4 < 16; ++d4) {
            ulonglong2 k0 = *(const ulonglong2*)(sKV + t * 68 + d4 * 4);
            ulonglong2 k1 = *(const ulonglong2*)(sKV + (t + 128) * 68 + d4 * 4);
            #pragma unroll
            for (int qi = 0; qi < 11; qi++) {
                ulonglong2 qv = *(const ulonglong2*)(sQ + qi * 64 + d4 * 4);
                lp0[qi] = fma2(qv.x, k0.x, lp0[qi]);
                lp0[qi] = fma2(qv.y, k0.y, lp0[qi]);
                lp1[qi] = fma2(qv.x, k1.x, lp1[qi]);
                lp1[qi] = fma2(qv.y, k1.y, lp1[qi]);
            }
        }
        float l0[11], l1[11];
        #pragma unroll
        for (int i = 0; i < 11; i++) {
            float2 u0 = unpk2(lp0[i]); l0[i] = u0.x + u0.y;
            float2 u1 = unpk2(lp1[i]); l1[i] = u1.x + u1.y;
        }
        float mx0 = l0[0], mx1 = l1[0];
        #pragma unroll
        for (int i = 1; i < 11; i++) { mx0 = fmaxf(mx0, l0[i]); mx1 = fmaxf(mx1, l1[i]); }
        float sum0 = 0.f, sum1 = 0.f;
        #pragma unroll
        for (int i = 0; i < 11; i++) {
            l0[i] = __expf(l0[i] - mx0); sum0 += l0[i];
            l1[i] = __expf(l1[i] - mx1); sum1 += l1[i];
        }
        float inv0 = 1.f / sum0, inv1 = 1.f / sum1;
        float gx0 = sG[2 * t], gy0 = sG[2 * t + 1];
        float gx1 = sG[2 * (t + 128)], gy1 = sG[2 * (t + 128) + 1];
        float gxx0 = gx0 * gx0, gyy0 = gy0 * gy0;
        float gxx1 = gx1 * gx1, gyy1 = gy1 * gy1;
        #pragma unroll
        for (int i = 0; i < 11; i++) {
            float a0 = l0[i] * inv0;
            float a1 = l1[i] * inv1;
            sA[t * 12 + i]         = a0;
            sA[(t + 128) * 12 + i] = a1;
            sS[i] += a0 + a1;
            if (last) {
                a1x[i] += a0 * gx0 + a1 * gx1;
                a1y[i] += a0 * gy0 + a1 * gy1;
                a2x[i] += a0 * gxx0 + a1 * gxx1;
                a2y[i] += a0 * gyy0 + a1 * gyy1;
            }
        }
        sA[t * 12 + 11] = 0.f;
        sA[(t + 128) * 12 + 11] = 0.f;
        __syncthreads();

        // V tile (reuse sKV)
        const uint4* gv = (const uint4*)(g_vh + ((size_t)b * KK + kb) * 64);
        for (int i = t; i < 2048; i += 128) {
            uint4 hv = gv[i];
            int row = i >> 3, cc = (i & 7) * 8;
            float2 f0 = __half22float2(*(__half2*)&hv.x);
            float2 f1 = __half22float2(*(__half2*)&hv.y);
            float2 f2 = __half22float2(*(__half2*)&hv.z);
            float2 f3 = __half22float2(*(__half2*)&hv.w);
            float* dst = sKV + row * 68 + cc;
            *(float4*)dst       = make_float4(f0.x, f0.y, f1.x, f1.y);
            *(float4*)(dst + 4) = make_float4(f2.x, f2.y, f3.x, f3.y);
        }
        __syncthreads();

        // rank-1: warps 0-2, 4 slots each (slot 11 is zero pad)
        if (qw < 3) {
            #pragma unroll 4
            for (int key = 0; key < 256; ++key) {
                float4 a4 = *(const float4*)(sA + key * 12 + qw * 4);
                float v0 = sKV[key * 68 + dg];
                float v1 = sKV[key * 68 + dg + 32];
                aU[0][0] += a4.x * v0; aU[0][1] += a4.x * v1;
                aU[1][0] += a4.y * v0; aU[1][1] += a4.y * v1;
                aU[2][0] += a4.z * v0; aU[2][1] += a4.z * v1;
                aU[3][0] += a4.w * v0; aU[3][1] += a4.w * v1;
            }
        }
    }

    __syncthreads();
    float* red = sKV;
    size_t base = ((size_t)b * CPB + c) * NACC;
    if (qw < 3) {
        #pragma unroll
        for (int i = 0; i < 4; i++) {
            int q = qw * 4 + i;
            if (q < 11) {
                g_part[base + q * 64 + dg]      = aU[i][0];
                g_part[base + q * 64 + dg + 32] = aU[i][1];
            }
        }
    }
    int w = t >> 5, lane = t & 31;
    #define RED1(v, slot) { float _x = (v); \
        _Pragma("unroll") for (int _o = 16; _o; _o >>= 1) _x += __shfl_xor_sync(0xffffffffu, _x, _o); \
        if (lane == 0) red[w * 64 + (slot)] = _x; }
    #pragma unroll
    for (int i = 0; i < 11; i++) RED1(sS[i], i);
    if (last) {
        #pragma unroll
        for (int i = 0; i < 11; i++) {
            RED1(a1x[i], 11 + i); RED1(a1y[i], 22 + i);
            RED1(a2x[i], 33 + i); RED1(a2y[i], 44 + i);
        }
    }
    #undef RED1
    __syncthreads();
    int nvals = last ? 55 : 11;
    if (t < nvals) {
        float tot = red[t] + red[64 + t] + red[128 + t] + red[192 + t];
        int off;
        if (t < 11)      off = 704 + t;
        else if (t < 22) off = 715 + (t - 11) * 2;
        else if (t < 33) off = 716 + (t - 22) * 2;
        else if (t < 44) off = 737 + (t - 33) * 2;
        else             off = 738 + (t - 44) * 2;
        g_part[base + off] = tot;
    }
}

// ================= GRU + MLP update (smem-staged weights, R5 form) ==============
// grid: 88 blocks x 512 threads, 8 rows/block, 176KB dynamic smem
__global__ void __launch_bounds__(512) upd_kernel(
    const float* __restrict__ Wir, const float* __restrict__ Wiz, const float* __restrict__ Win,
    const float* __restrict__ bir, const float* __restrict__ biz, const float* __restrict__ binp,
    const float* __restrict__ Whr, const float* __restrict__ Whz, const float* __restrict__ Whn,
    const float* __restrict__ bhn, const float* __restrict__ mls, const float* __restrict__ mlb,
    const float* __restrict__ W1, const float* __restrict__ b1,
    const float* __restrict__ W2, const float* __restrict__ b2,
    const float* __restrict__ Wq, const float* __restrict__ qs, const float* __restrict__ qb,
    float* __restrict__ outp, int last)
{
    extern __shared__ float ws[];   // [Wir|Wiz|Win|Whr|Whz|Whn|W1|W2|Wq]
    __shared__ float s_upd[8][64], s_sl[8][64], s_xn[8][64], s_hb[8][128];
    __shared__ float s_red[8][2];

    int tid = threadIdx.x;
    for (int i = tid; i < 11264; i += 512) {
        float4 val;
        if      (i < 1024)  val = ((const float4*)Wir)[i];
        else if (i < 2048)  val = ((const float4*)Wiz)[i - 1024];
        else if (i < 3072)  val = ((const float4*)Win)[i - 2048];
        else if (i < 4096)  val = ((const float4*)Whr)[i - 3072];
        else if (i < 5120)  val = ((const float4*)Whz)[i - 4096];
        else if (i < 6144)  val = ((const float4*)Whn)[i - 5120];
        else if (i < 8192)  val = ((const float4*)W1)[i - 6144];
        else if (i < 10240) val = ((const float4*)W2)[i - 8192];
        else                val = ((const float4*)Wq)[i - 10240];
        ((float4*)ws)[i] = val;
    }

    int r = tid >> 6, t = tid & 63;
    int bq = blockIdx.x * 8 + r;
    int b = bq / 11, q = bq - b * 11;
    const float* pb = g_part + (size_t)b * CPB * NACC;

    float U = 0.f, S = 0.f;
    #pragma unroll
    for (int cc = 0; cc < CPB; cc++) {
        U += pb[cc * NACC + q * 64 + t];
        S += pb[cc * NACC + 704 + q];
    }
    float u = U / (S + 1e-8f);
    s_upd[r][t] = u;
    float slv = g_slots[bq * 64 + t];
    s_sl[r][t] = slv;
    __syncthreads();   // covers ws staging too

    float air = bir[t], aiz = biz[t], ain = binp[t];
    float ahr = 0.f, ahz = 0.f, ahn = bhn[t];
    const float* wir = ws;
    const float* wiz = ws + 4096;
    const float* win = ws + 8192;
    const float* whr = ws + 12288;
    const float* whz = ws + 16384;
    const float* whn = ws + 20480;
    #pragma unroll 4
    for (int d = 0; d < 64; ++d) {
        float ud = s_upd[r][d], sd = s_sl[r][d];
        air += ud * wir[d * 64 + t];
        aiz += ud * wiz[d * 64 + t];
        ain += ud * win[d * 64 + t];
        ahr += sd * whr[d * 64 + t];
        ahz += sd * whz[d * 64 + t];
        ahn += sd * whn[d * 64 + t];
    }
    float rg = 1.f / (1.f + __expf(-(air + ahr)));
    float zg = 1.f / (1.f + __expf(-(aiz + ahz)));
    float ng = tanhf(ain + rg * ahn);
    float snew = (1.f - zg) * ng + zg * slv;

    float m = rowsum64(snew, t, s_red[r]) * (1.f / 64.f);
    float dv = snew - m;
    float var = rowsum64(dv * dv, t, s_red[r]) * (1.f / 64.f);
    float x = dv * rsqrtf(var + 1e-6f) * mls[t] + mlb[t];
    s_xn[r][t] = x;
    __syncthreads();
    const float* w1 = ws + 24576;
    float h0 = b1[t], h1 = b1[64 + t];
    #pragma unroll 4
    for (int d = 0; d < 64; ++d) {
        float xd = s_xn[r][d];
        h0 += xd * w1[d * 128 + t];
        h1 += xd * w1[d * 128 + 64 + t];
    }
    s_hb[r][t] = fmaxf(h0, 0.f);
    s_hb[r][64 + t] = fmaxf(h1, 0.f);
    __syncthreads();
    const float* w2 = ws + 32768;
    float od = snew + b2[t];
    #pragma unroll 4
    for (int hh = 0; hh < 128; ++hh) od += s_hb[r][hh] * w2[hh * 64 + t];

    if (!last) {
        g_slots[bq * 64 + t] = od;
        float qm = rowsum64(od, t, s_red[r]) * (1.f / 64.f);
        float qd = od - qm;
        float qvar = rowsum64(qd * qd, t, s_red[r]) * (1.f / 64.f);
        float xq = qd * rsqrtf(qvar + 1e-6f) * qs[t] + qb[t];
        s_xn[r][t] = xq;
        __syncthreads();
        const float* wq = ws + 40960;
        float acc = 0.f;
        #pragma unroll 4
        for (int d = 0; d < 64; ++d) acc += s_xn[r][d] * wq[d * 64 + t];
        g_q[bq * 64 + t] = acc * 0.125f;
        return;
    }

    outp[bq * 68 + t] = od;
    if (t == 0) {
        float4 gm = *(const float4*)(g_gm + b * 4);
        float s1x = gm.x, s1y = gm.y, s2x = gm.z, s2y = gm.w;
        float A1xv = 0.f, A1yv = 0.f, A2xv = 0.f, A2yv = 0.f;
        #pragma unroll
        for (int cc = 0; cc < CPB; cc++) {
            A1xv += pb[cc * NACC + 715 + q * 2];
            A1yv += pb[cc * NACC + 716 + q * 2];
            A2xv += pb[cc * NACC + 737 + q * 2];
            A2yv += pb[cc * NACC + 738 + q * 2];
        }
        float inv = 1.f / (S + 1e-8f);
        float px = A1xv * inv, py = A1yv * inv;
        float T = S * inv;
        float vx = A2xv * inv - px * px * (2.f - T)
                 + 1e-8f * (s2x - 2.f * px * s1x + 4096.f * px * px);
        float vy = A2yv * inv - py * py * (2.f - T)
                 + 1e-8f * (s2y - 2.f * py * s1y + 4096.f * py * py);
        float scx = fminf(fmaxf(sqrtf(fmaxf(vx, 0.f)), 0.01f), 5.f);
        float scy = fminf(fmaxf(sqrtf(fmaxf(vy, 0.f)), 0.01f), 5.f);
        outp[bq * 68 + 64] = px;
        outp[bq * 68 + 65] = py;
        outp[bq * 68 + 66] = scx;
        outp[bq * 68 + 67] = scy;
    }
}

// ================= launch =================
extern "C" void kernel_launch(void* const* d_in, const int* in_sizes, int n_in,
                              void* d_out, int out_size)
{
    (void)in_sizes; (void)n_in; (void)out_size;
    const float* slots  = (const float*)d_in[0];
    const float* inputs = (const float*)d_in[1];
    const float* Wpe  = (const float*)d_in[2];
    const float* bpe  = (const float*)d_in[3];
    const float* ges  = (const float*)d_in[4];
    const float* geb  = (const float*)d_in[5];
    const float* ins  = (const float*)d_in[6];
    const float* inb  = (const float*)d_in[7];
    const float* Wk   = (const float*)d_in[8];
    const float* Wv   = (const float*)d_in[9];
    const float* qs   = (const float*)d_in[10];
    const float* qb   = (const float*)d_in[11];
    const float* Wq   = (const float*)d_in[12];
    const float* Wir  = (const float*)d_in[13];
    const float* Wiz  = (const float*)d_in[14];
    const float* Win  = (const float*)d_in[15];
    const float* bir  = (const float*)d_in[16];
    const float* biz  = (const float*)d_in[17];
    const float* binp = (const float*)d_in[18];
    const float* Whr  = (const float*)d_in[19];
    const float* Whz  = (const float*)d_in[20];
    const float* Whn  = (const float*)d_in[21];
    const float* bhn  = (const float*)d_in[22];
    const float* mls  = (const float*)d_in[23];
    const float* mlb  = (const float*)d_in[24];
    const float* W1   = (const float*)d_in[25];
    const float* b1   = (const float*)d_in[26];
    const float* W2   = (const float*)d_in[27];
    const float* b2   = (const float*)d_in[28];
    float* out = (float*)d_out;

    cudaFuncSetAttribute(prep_kernel, cudaFuncAttributeMaxDynamicSharedMemorySize, PREP_SMEM);
    cudaFuncSetAttribute(attn_kernel, cudaFuncAttributeMaxDynamicSharedMemorySize, ATTN_SMEM);
    cudaFuncSetAttribute(upd_kernel,  cudaFuncAttributeMaxDynamicSharedMemorySize, UPD_SMEM);

    prep_kernel<<<BB * 32, 256, PREP_SMEM>>>(inputs, Wpe, bpe, ges, geb, ins, inb, Wk, Wv);
    gstats_kernel<<<BB, 256>>>();
    q_kernel<<<BB * QQ, 64>>>(slots, qs, qb, Wq);
    for (int it = 0; it < NITER; ++it) {
        int last = (it == NITER - 1);
        attn_kernel<<<BB * CPB, 128, ATTN_SMEM>>>(last);
        upd_kernel<<<BB * QQ / 8, 512, UPD_SMEM>>>(Wir, Wiz, Win, bir, biz, binp,
                                                   Whr, Whz, Whn, bhn, mls, mlb,
                                                   W1, b1, W2, b2, Wq, qs, qb, out, last);
    }
}

// round 10
// speedup vs baseline: 1.6040x; 1.0531x over previous
// R10: R8 attn design de-risked — cp.async removed (plain LDG->STS V fill),
// LAST templated out of hot launches, __launch_bounds__(256,2) caps regs at 128
// so 2 CTAs/SM (16 warps) actually materialize. prep/gstats/q/upd = R7 passing code.
#include <cuda_runtime.h>
#include <cuda_fp16.h>

#define BB 64
#define KK 4096
#define DD 64
#define QQ 11
#define HH 128
#define NITER 3
#define CPB 8
#define NACC 768         // per-CTA partial record (704 U + 11 S + 22 A1 + 22 A2)

#define PREP_SMEM ((8192 + 8704) * 4)          // sW 64x128 + sX 64x136
#define ATTN_SMEM (14016 * 4)                  // sQ 704 + sV 9216(f-equiv) + sA 4096
#define UPD_SMEM  (45056 * 4)   // 6x4096 GRU + W1 8192 + W2 8192 + Wq 4096

typedef unsigned long long ull;

__device__ __forceinline__ ull pack2(float x, float y) {
    ull r; asm("mov.b64 %0,{%1,%2};" : "=l"(r) : "f"(x), "f"(y)); return r;
}
__device__ __forceinline__ ull fma2(ull a, ull b, ull c) {
    ull d; asm("fma.rn.f32x2 %0,%1,%2,%3;" : "=l"(d) : "l"(a), "l"(b), "l"(c)); return d;
}
__device__ __forceinline__ float2 unpk2(ull v) {
    float2 f; asm("mov.b64 {%0,%1},%2;" : "=f"(f.x), "=f"(f.y) : "l"(v)); return f;
}

// ---------------- scratch ----------------
__device__ __align__(16) __half g_kh[BB * KK * DD];   // 32 MB
__device__ __align__(16) __half g_vh[BB * KK * DD];   // 32 MB
__device__ __align__(16) float g_grid[BB * KK * 2];
__device__ __align__(16) float g_slots[BB * QQ * DD];
__device__ __align__(16) float g_q[BB * QQ * DD];
__device__ __align__(16) float g_part[BB * CPB * NACC];
__device__ __align__(16) float g_gm[BB * 4];          // per-batch sum g, sum g^2

__device__ __forceinline__ float bsum64(float v, volatile float* red) {
    #pragma unroll
    for (int o = 16; o; o >>= 1) v += __shfl_xor_sync(0xffffffffu, v, o);
    int t = threadIdx.x;
    if ((t & 31) == 0) red[t >> 5] = v;
    __syncthreads();
    float r = red[0] + red[1];
    __syncthreads();
    return r;
}
__device__ __forceinline__ float rowsum64(float v, int t, volatile float* red2) {
    #pragma unroll
    for (int o = 16; o; o >>= 1) v += __shfl_xor_sync(0xffffffffu, v, o);
    if ((t & 31) == 0) red2[t >> 5] = v;
    __syncthreads();
    float r = red2[0] + red2[1];
    __syncthreads();
    return r;
}

// ================= Kernel 1: PE + 2x LN + K/V projection (f32x2 GEMM) ==========
__global__ void __launch_bounds__(256) prep_kernel(
    const float* __restrict__ in, const float* __restrict__ Wpe, const float* __restrict__ bpe,
    const float* __restrict__ ges, const float* __restrict__ geb,
    const float* __restrict__ ins, const float* __restrict__ inb,
    const float* __restrict__ Wk, const float* __restrict__ Wv)
{
    extern __shared__ float dsm[];
    float* sW = dsm;              // [64 d][128 cols] 0..63 Wk, 64..127 Wv
    float* sX = dsm + 8192;       // [64 d][rows], stride 136

    int t = threadIdx.x;
    int bid = blockIdx.x;
    int b = bid >> 5;
    int row0 = (bid & 31) * 128;

    for (int i = t; i < 8192; i += 256) {
        int d = i >> 7, col = i & 127;
        sW[i] = (col < 64) ? Wk[d * 64 + col] : Wv[d * 64 + col - 64];
    }
    int lane = t & 31;
    int w = t >> 5;

    float pe00 = Wpe[lane],      pe01 = Wpe[32 + lane];
    float pe10 = Wpe[64 + lane], pe11 = Wpe[96 + lane];
    float bp0 = bpe[lane],  bp1 = bpe[32 + lane];
    float gs0 = ges[lane],  gs1 = ges[32 + lane];
    float gb0 = geb[lane],  gb1 = geb[32 + lane];
    float is0 = ins[lane],  is1 = ins[32 + lane];
    float ib0 = inb[lane],  ib1 = inb[32 + lane];

    for (int r = 0; r < 16; ++r) {
        int lrow = w * 16 + r;
        int row = row0 + lrow;
        const float* src = in + (size_t)(b * KK + row) * 66;
        float f0 = src[lane], f1 = src[32 + lane];
        float gx = src[64], gy = src[65];
        float x0 = f0 + gx * pe00 + gy * pe10 + bp0;
        float x1 = f1 + gx * pe01 + gy * pe11 + bp1;

        float s = x0 + x1;
        #pragma unroll
        for (int o = 16; o; o >>= 1) s += __shfl_xor_sync(0xffffffffu, s, o);
        float m = s * (1.f / 64.f);
        float d0 = x0 - m, d1 = x1 - m;
        float vv = d0 * d0 + d1 * d1;
        #pragma unroll
        for (int o = 16; o; o >>= 1) vv += __shfl_xor_sync(0xffffffffu, vv, o);
        float inv = rsqrtf(vv * (1.f / 64.f) + 1e-6f);
        x0 = d0 * inv * gs0 + gb0;
        x1 = d1 * inv * gs1 + gb1;

        s = x0 + x1;
        #pragma unroll
        for (int o = 16; o; o >>= 1) s += __shfl_xor_sync(0xffffffffu, s, o);
        m = s * (1.f / 64.f);
        d0 = x0 - m; d1 = x1 - m;
        vv = d0 * d0 + d1 * d1;
        #pragma unroll
        for (int o = 16; o; o >>= 1) vv += __shfl_xor_sync(0xffffffffu, vv, o);
        inv = rsqrtf(vv * (1.f / 64.f) + 1e-6f);
        x0 = d0 * inv * is0 + ib0;
        x1 = d1 * inv * is1 + ib1;

        sX[lane * 136 + lrow]        = x0;
        sX[(lane + 32) * 136 + lrow] = x1;
        if (lane == 0) {
            g_grid[(b * KK + row) * 2]     = gx;
            g_grid[(b * KK + row) * 2 + 1] = gy;
        }
    }
    __syncthreads();

    int cg = t & 15, rg = t >> 4;
    int c0 = cg * 8, r0 = rg * 8;
    ull acc2[8][4];
    #pragma unroll
    for (int i = 0; i < 8; i++)
        #pragma unroll
        for (int j = 0; j < 4; j++) acc2[i][j] = 0ull;

    #pragma unroll 2
    for (int d = 0; d < 64; ++d) {
        const float* xr = sX + d * 136 + r0;
        float4 xa = *(const float4*)xr;
        float4 xb = *(const float4*)(xr + 4);
        ull xp[8];
        xp[0] = pack2(xa.x, xa.x); xp[1] = pack2(xa.y, xa.y);
        xp[2] = pack2(xa.z, xa.z); xp[3] = pack2(xa.w, xa.w);
        xp[4] = pack2(xb.x, xb.x); xp[5] = pack2(xb.y, xb.y);
        xp[6] = pack2(xb.z, xb.z); xp[7] = pack2(xb.w, xb.w);
        ulonglong2 wa = *(const ulonglong2*)(sW + d * 128 + c0);
        ulonglong2 wb = *(const ulonglong2*)(sW + d * 128 + c0 + 4);
        #pragma unroll
        for (int i = 0; i < 8; i++) {
            acc2[i][0] = fma2(xp[i], wa.x, acc2[i][0]);
            acc2[i][1] = fma2(xp[i], wa.y, acc2[i][1]);
            acc2[i][2] = fma2(xp[i], wb.x, acc2[i][2]);
            acc2[i][3] = fma2(xp[i], wb.y, acc2[i][3]);
        }
    }

    size_t gbase = (size_t)(b * KK + row0 + r0) * 64;
    #pragma unroll
    for (int i = 0; i < 8; i++) {
        float2 p0 = unpk2(acc2[i][0]), p1 = unpk2(acc2[i][1]);
        float2 p2 = unpk2(acc2[i][2]), p3 = unpk2(acc2[i][3]);
        __half2 h0 = __floats2half2_rn(p0.x, p0.y);
        __half2 h1 = __floats2half2_rn(p1.x, p1.y);
        __half2 h2 = __floats2half2_rn(p2.x, p2.y);
        __half2 h3 = __floats2half2_rn(p3.x, p3.y);
        uint4 pk;
        pk.x = *(unsigned*)&h0; pk.y = *(unsigned*)&h1;
        pk.z = *(unsigned*)&h2; pk.w = *(unsigned*)&h3;
        size_t off = gbase + (size_t)i * 64;
        if (cg < 8) *(uint4*)(g_kh + off + c0)      = pk;
        else        *(uint4*)(g_vh + off + c0 - 64) = pk;
    }
}

// ================= gstats =================
__global__ void __launch_bounds__(256) gstats_kernel()
{
    __shared__ float4 sred[8];
    int b = blockIdx.x, t = threadIdx.x;
    float s1x = 0.f, s1y = 0.f, s2x = 0.f, s2y = 0.f;
    const float2* gg = (const float2*)(g_grid + (size_t)b * KK * 2);
    for (int k = t; k < KK; k += 256) {
        float2 g = gg[k];
        s1x += g.x; s1y += g.y; s2x += g.x * g.x; s2y += g.y * g.y;
    }
    #pragma unroll
    for (int o = 16; o; o >>= 1) {
        s1x += __shfl_xor_sync(0xffffffffu, s1x, o);
        s1y += __shfl_xor_sync(0xffffffffu, s1y, o);
        s2x += __shfl_xor_sync(0xffffffffu, s2x, o);
        s2y += __shfl_xor_sync(0xffffffffu, s2y, o);
    }
    if ((t & 31) == 0) sred[t >> 5] = make_float4(s1x, s1y, s2x, s2y);
    __syncthreads();
    if (t == 0) {
        float4 a = sred[0];
        #pragma unroll
        for (int i = 1; i < 8; i++) {
            a.x += sred[i].x; a.y += sred[i].y; a.z += sred[i].z; a.w += sred[i].w;
        }
        *(float4*)(g_gm + b * 4) = a;
    }
}

// ================= iter-0 q projection =================
__global__ void __launch_bounds__(64) q_kernel(
    const float* __restrict__ slots_in, const float* __restrict__ qs,
    const float* __restrict__ qb, const float* __restrict__ Wq)
{
    __shared__ float xs[64];
    __shared__ float red[2];
    int row = blockIdx.x, t = threadIdx.x;
    float sv = slots_in[row * 68 + t];
    g_slots[row * 64 + t] = sv;
    float m = bsum64(sv, red) * (1.f / 64.f);
    float dv = sv - m;
    float var = bsum64(dv * dv, red) * (1.f / 64.f);
    float xn = dv * rsqrtf(var + 1e-6f) * qs[t] + qb[t];
    xs[t] = xn;
    __syncthreads();
    float acc = 0.f;
    #pragma unroll
    for (int d = 0; d < 64; ++d) acc += xs[d] * Wq[d * 64 + t];
    g_q[row * 64 + t] = acc * 0.125f;
}

// ================= attention v3: 512 CTAs x 256 threads, 2 tiles of 256 keys ===
// K rows gmem->regs; V fp16 smem via plain LDG->STS; LAST templated.
template<int LAST>
__global__ void __launch_bounds__(256, 2) attn_kernel()
{
    extern __shared__ float dsm[];
    float*  sQ = dsm;                        // 704 floats
    __half* sV = (__half*)(dsm + 704);       // 256 rows x 72 halves (stride 144B)
    float*  sA = dsm + 704 + 9216;           // 256 x 16 floats

    int t = threadIdx.x;
    int b = blockIdx.x >> 3, c = blockIdx.x & 7;
    int key0 = c * 512;

    for (int i = t; i < 704; i += 256) sQ[i] = g_q[b * 704 + i];

    // rank-1 role: 3 active warps (t<96), warp g handles slots 4g..4g+3, d-pairs by lane
    int g = t >> 5, lane = t & 31;
    bool act = (t < 96);

    ull acc[2][2] = {{0ull,0ull},{0ull,0ull}};  // [d0/d1][slotpair01/23]
    float sS[11];
    float a1x[LAST ? 11 : 1], a1y[LAST ? 11 : 1];
    float a2x[LAST ? 11 : 1], a2y[LAST ? 11 : 1];
    #pragma unroll
    for (int i = 0; i < 11; i++) sS[i] = 0.f;
    if (LAST) {
        #pragma unroll
        for (int i = 0; i < 11; i++) { a1x[i]=0.f; a1y[i]=0.f; a2x[i]=0.f; a2y[i]=0.f; }
    }

    for (int tile = 0; tile < 2; ++tile) {
        int kb = key0 + tile * 256;
        int kt = kb + t;
        __syncthreads();   // previous tile's sV/sA fully consumed; sQ ready (tile 0)

        // V tile: 256 rows x 128B fp16, plain coalesced LDG.128 -> STS.128
        {
            const uint4* vsrc = (const uint4*)(g_vh + ((size_t)b * KK + kb) * 64);
            #pragma unroll
            for (int k = 0; k < 8; ++k) {
                int i = t + k * 256;
                int row = i >> 3, cc = i & 7;
                *(uint4*)((char*)sV + row * 144 + cc * 16) = vsrc[i];
            }
        }

        // K row for my key: 8 x LDG.128 coalesced
        const uint4* krow = (const uint4*)(g_kh + ((size_t)b * KK + kt) * 64);

        // logits over 11 slots, f32x2; K consumed chunk-by-chunk (keeps regs low)
        ull lp[11];
        #pragma unroll
        for (int i = 0; i < 11; i++) lp[i] = 0ull;
        #pragma unroll
        for (int ch = 0; ch < 8; ++ch) {
            uint4 kc = krow[ch];
            float2 f0 = __half22float2(*(__half2*)&kc.x);
            float2 f1 = __half22float2(*(__half2*)&kc.y);
            float2 f2 = __half22float2(*(__half2*)&kc.z);
            float2 f3 = __half22float2(*(__half2*)&kc.w);
            ull k0 = pack2(f0.x, f0.y), k1 = pack2(f1.x, f1.y);
            ull k2 = pack2(f2.x, f2.y), k3 = pack2(f3.x, f3.y);
            #pragma unroll
            for (int qi = 0; qi < 11; qi++) {
                ulonglong2 qlo = *(const ulonglong2*)(sQ + qi * 64 + ch * 8);
                ulonglong2 qhi = *(const ulonglong2*)(sQ + qi * 64 + ch * 8 + 4);
                lp[qi] = fma2(qlo.x, k0, lp[qi]);
                lp[qi] = fma2(qlo.y, k1, lp[qi]);
                lp[qi] = fma2(qhi.x, k2, lp[qi]);
                lp[qi] = fma2(qhi.y, k3, lp[qi]);
            }
        }
        float l[11];
        #pragma unroll
        for (int i = 0; i < 11; i++) { float2 u = unpk2(lp[i]); l[i] = u.x + u.y; }
        float mx = l[0];
        #pragma unroll
        for (int i = 1; i < 11; i++) mx = fmaxf(mx, l[i]);
        float sum = 0.f;
        #pragma unroll
        for (int i = 0; i < 11; i++) { l[i] = __expf(l[i] - mx); sum += l[i]; }
        float inv = 1.f / sum;
        #pragma unroll
        for (int i = 0; i < 11; i++) {
            float a = l[i] * inv;
            sA[t * 16 + i] = a;
            sS[i] += a;
        }
        sA[t * 16 + 11] = 0.f;
        if (LAST) {
            float2 gr = ((const float2*)g_grid)[(size_t)b * KK + kt];
            float gxx = gr.x * gr.x, gyy = gr.y * gr.y;
            #pragma unroll
            for (int i = 0; i < 11; i++) {
                float a = l[i] * inv;
                a1x[i] += a * gr.x; a1y[i] += a * gr.y;
                a2x[i] += a * gxx;  a2y[i] += a * gyy;
            }
        }
        __syncthreads();   // sV fills + sA writes visible to rank-1

        // rank-1: per key, a-pair broadcast (16B) + v half2, 4 x fma2
        if (act) {
            #pragma unroll 4
            for (int key = 0; key < 256; ++key) {
                ulonglong2 ap = *(const ulonglong2*)(sA + key * 16 + g * 4);  // (a0,a1),(a2,a3)
                float2 vf = __half22float2(*(const __half2*)(sV + key * 72 + lane * 2));
                ull p0 = pack2(vf.x, vf.x);
                ull p1 = pack2(vf.y, vf.y);
                acc[0][0] = fma2(ap.x, p0, acc[0][0]);
                acc[0][1] = fma2(ap.y, p0, acc[0][1]);
                acc[1][0] = fma2(ap.x, p1, acc[1][0]);
                acc[1][1] = fma2(ap.y, p1, acc[1][1]);
            }
        }
    }

    __syncthreads();
    size_t base = ((size_t)b * CPB + c) * NACC;
    if (act) {
        float2 u00 = unpk2(acc[0][0]);   // (U[4g+0][d0], U[4g+1][d0])
        float2 u01 = unpk2(acc[0][1]);   // (U[4g+2][d0], U[4g+3][d0])
        float2 u10 = unpk2(acc[1][0]);
        float2 u11 = unpk2(acc[1][1]);
        int q0 = g * 4;
        int d0 = lane * 2, d1 = lane * 2 + 1;
        g_part[base + (q0 + 0) * 64 + d0] = u00.x;
        g_part[base + (q0 + 1) * 64 + d0] = u00.y;
        g_part[base + (q0 + 2) * 64 + d0] = u01.x;
        g_part[base + (q0 + 0) * 64 + d1] = u10.x;
        g_part[base + (q0 + 1) * 64 + d1] = u10.y;
        g_part[base + (q0 + 2) * 64 + d1] = u11.x;
        if (q0 + 3 < 11) {
            g_part[base + (q0 + 3) * 64 + d0] = u01.y;
            g_part[base + (q0 + 3) * 64 + d1] = u11.y;
        }
    }

    // reductions across 8 warps (red reuses sV region)
    float* red = (float*)sV;
    int w = t >> 5, lanew = t & 31;
    #define RED1(v, slot) { float _x = (v); \
        _Pragma("unroll") for (int _o = 16; _o; _o >>= 1) _x += __shfl_xor_sync(0xffffffffu, _x, _o); \
        if (lanew == 0) red[w * 64 + (slot)] = _x; }
    #pragma unroll
    for (int i = 0; i < 11; i++) RED1(sS[i], i);
    if (LAST) {
        #pragma unroll
        for (int i = 0; i < 11; i++) {
            RED1(a1x[i], 11 + i); RED1(a1y[i], 22 + i);
            RED1(a2x[i], 33 + i); RED1(a2y[i], 44 + i);
        }
    }
    #undef RED1
    __syncthreads();
    int nvals = LAST ? 55 : 11;
    if (t < nvals) {
        float tot = 0.f;
        #pragma unroll
        for (int k = 0; k < 8; k++) tot += red[k * 64 + t];
        int off;
        if (t < 11)      off = 704 + t;
        else if (t < 22) off = 715 + (t - 11) * 2;
        else if (t < 33) off = 716 + (t - 22) * 2;
        else if (t < 44) off = 737 + (t - 33) * 2;
        else             off = 738 + (t - 44) * 2;
        g_part[base + off] = tot;
    }
}

// ================= GRU + MLP update (smem-staged weights) =======================
__global__ void __launch_bounds__(512) upd_kernel(
    const float* __restrict__ Wir, const float* __restrict__ Wiz, const float* __restrict__ Win,
    const float* __restrict__ bir, const float* __restrict__ biz, const float* __restrict__ binp,
    const float* __restrict__ Whr, const float* __restrict__ Whz, const float* __restrict__ Whn,
    const float* __restrict__ bhn, const float* __restrict__ mls, const float* __restrict__ mlb,
    const float* __restrict__ W1, const float* __restrict__ b1,
    const float* __restrict__ W2, const float* __restrict__ b2,
    const float* __restrict__ Wq, const float* __restrict__ qs, const float* __restrict__ qb,
    float* __restrict__ outp, int last)
{
    extern __shared__ float ws[];   // [Wir|Wiz|Win|Whr|Whz|Whn|W1|W2|Wq]
    __shared__ float s_upd[8][64], s_sl[8][64], s_xn[8][64], s_hb[8][128];
    __shared__ float s_red[8][2];

    int tid = threadIdx.x;
    for (int i = tid; i < 11264; i += 512) {
        float4 val;
        if      (i < 1024)  val = ((const float4*)Wir)[i];
        else if (i < 2048)  val = ((const float4*)Wiz)[i - 1024];
        else if (i < 3072)  val = ((const float4*)Win)[i - 2048];
        else if (i < 4096)  val = ((const float4*)Whr)[i - 3072];
        else if (i < 5120)  val = ((const float4*)Whz)[i - 4096];
        else if (i < 6144)  val = ((const float4*)Whn)[i - 5120];
        else if (i < 8192)  val = ((const float4*)W1)[i - 6144];
        else if (i < 10240) val = ((const float4*)W2)[i - 8192];
        else                val = ((const float4*)Wq)[i - 10240];
        ((float4*)ws)[i] = val;
    }

    int r = tid >> 6, t = tid & 63;
    int bq = blockIdx.x * 8 + r;
    int b = bq / 11, q = bq - b * 11;
    const float* pb = g_part + (size_t)b * CPB * NACC;

    float U = 0.f, S = 0.f;
    #pragma unroll
    for (int cc = 0; cc < CPB; cc++) {
        U += pb[cc * NACC + q * 64 + t];
        S += pb[cc * NACC + 704 + q];
    }
    float u = U / (S + 1e-8f);
    s_upd[r][t] = u;
    float slv = g_slots[bq * 64 + t];
    s_sl[r][t] = slv;
    __syncthreads();

    float air = bir[t], aiz = biz[t], ain = binp[t];
    float ahr = 0.f, ahz = 0.f, ahn = bhn[t];
    const float* wir = ws;
    const float* wiz = ws + 4096;
    const float* win = ws + 8192;
    const float* whr = ws + 12288;
    const float* whz = ws + 16384;
    const float* whn = ws + 20480;
    #pragma unroll 4
    for (int d = 0; d < 64; ++d) {
        float ud = s_upd[r][d], sd = s_sl[r][d];
        air += ud * wir[d * 64 + t];
        aiz += ud * wiz[d * 64 + t];
        ain += ud * win[d * 64 + t];
        ahr += sd * whr[d * 64 + t];
        ahz += sd * whz[d * 64 + t];
        ahn += sd * whn[d * 64 + t];
    }
    float rg = 1.f / (1.f + __expf(-(air + ahr)));
    float zg = 1.f / (1.f + __expf(-(aiz + ahz)));
    float ng = tanhf(ain + rg * ahn);
    float snew = (1.f - zg) * ng + zg * slv;

    float m = rowsum64(snew, t, s_red[r]) * (1.f / 64.f);
    float dv = snew - m;
    float var = rowsum64(dv * dv, t, s_red[r]) * (1.f / 64.f);
    float x = dv * rsqrtf(var + 1e-6f) * mls[t] + mlb[t];
    s_xn[r][t] = x;
    __syncthreads();
    const float* w1 = ws + 24576;
    float h0 = b1[t], h1 = b1[64 + t];
    #pragma unroll 4
    for (int d = 0; d < 64; ++d) {
        float xd = s_xn[r][d];
        h0 += xd * w1[d * 128 + t];
        h1 += xd * w1[d * 128 + 64 + t];
    }
    s_hb[r][t] = fmaxf(h0, 0.f);
    s_hb[r][64 + t] = fmaxf(h1, 0.f);
    __syncthreads();
    const float* w2 = ws + 32768;
    float od = snew + b2[t];
    #pragma unroll 4
    for (int hh = 0; hh < 128; ++hh) od += s_hb[r][hh] * w2[hh * 64 + t];

    if (!last) {
        g_slots[bq * 64 + t] = od;
        float qm = rowsum64(od, t, s_red[r]) * (1.f / 64.f);
        float qd = od - qm;
        float qvar = rowsum64(qd * qd, t, s_red[r]) * (1.f / 64.f);
        float xq = qd * rsqrtf(qvar + 1e-6f) * qs[t] + qb[t];
        s_xn[r][t] = xq;
        __syncthreads();
        const float* wq = ws + 40960;
        float acc = 0.f;
        #pragma unroll 4
        for (int d = 0; d < 64; ++d) acc += s_xn[r][d] * wq[d * 64 + t];
        g_q[bq * 64 + t] = acc * 0.125f;
        return;
    }

    outp[bq * 68 + t] = od;
    if (t == 0) {
        float4 gm = *(const float4*)(g_gm + b * 4);
        float s1x = gm.x, s1y = gm.y, s2x = gm.z, s2y = gm.w;
        float A1xv = 0.f, A1yv = 0.f, A2xv = 0.f, A2yv = 0.f;
        #pragma unroll
        for (int cc = 0; cc < CPB; cc++) {
            A1xv += pb[cc * NACC + 715 + q * 2];
            A1yv += pb[cc * NACC + 716 + q * 2];
            A2xv += pb[cc * NACC + 737 + q * 2];
            A2yv += pb[cc * NACC + 738 + q * 2];
        }
        float inv = 1.f / (S + 1e-8f);
        float px = A1xv * inv, py = A1yv * inv;
        float T = S * inv;
        float vx = A2xv * inv - px * px * (2.f - T)
                 + 1e-8f * (s2x - 2.f * px * s1x + 4096.f * px * px);
        float vy = A2yv * inv - py * py * (2.f - T)
                 + 1e-8f * (s2y - 2.f * py * s1y + 4096.f * py * py);
        float scx = fminf(fmaxf(sqrtf(fmaxf(vx, 0.f)), 0.01f), 5.f);
        float scy = fminf(fmaxf(sqrtf(fmaxf(vy, 0.f)), 0.01f), 5.f);
        outp[bq * 68 + 64] = px;
        outp[bq * 68 + 65] = py;
        outp[bq * 68 + 66] = scx;
        outp[bq * 68 + 67] = scy;
    }
}

// ================= launch =================
extern "C" void kernel_launch(void* const* d_in, const int* in_sizes, int n_in,
                              void* d_out, int out_size)
{
    (void)in_sizes; (void)n_in; (void)out_size;
    const float* slots  = (const float*)d_in[0];
    const float* inputs = (const float*)d_in[1];
    const float* Wpe  = (const float*)d_in[2];
    const float* bpe  = (const float*)d_in[3];
    const float* ges  = (const float*)d_in[4];
    const float* geb  = (const float*)d_in[5];
    const float* ins  = (const float*)d_in[6];
    const float* inb  = (const float*)d_in[7];
    const float* Wk   = (const float*)d_in[8];
    const float* Wv   = (const float*)d_in[9];
    const float* qs   = (const float*)d_in[10];
    const float* qb   = (const float*)d_in[11];
    const float* Wq   = (const float*)d_in[12];
    const float* Wir  = (const float*)d_in[13];
    const float* Wiz  = (const float*)d_in[14];
    const float* Win  = (const float*)d_in[15];
    const float* bir  = (const float*)d_in[16];
    const float* biz  = (const float*)d_in[17];
    const float* binp = (const float*)d_in[18];
    const float* Whr  = (const float*)d_in[19];
    const float* Whz  = (const float*)d_in[20];
    const float* Whn  = (const float*)d_in[21];
    const float* bhn  = (const float*)d_in[22];
    const float* mls  = (const float*)d_in[23];
    const float* mlb  = (const float*)d_in[24];
    const float* W1   = (const float*)d_in[25];
    const float* b1   = (const float*)d_in[26];
    const float* W2   = (const float*)d_in[27];
    const float* b2   = (const float*)d_in[28];
    float* out = (float*)d_out;

    cudaFuncSetAttribute(prep_kernel, cudaFuncAttributeMaxDynamicSharedMemorySize, PREP_SMEM);
    cudaFuncSetAttribute(attn_kernel<0>, cudaFuncAttributeMaxDynamicSharedMemorySize, ATTN_SMEM);
    cudaFuncSetAttribute(attn_kernel<1>, cudaFuncAttributeMaxDynamicSharedMemorySize, ATTN_SMEM);
    cudaFuncSetAttribute(upd_kernel,  cudaFuncAttributeMaxDynamicSharedMemorySize, UPD_SMEM);

    prep_kernel<<<BB * 32, 256, PREP_SMEM>>>(inputs, Wpe, bpe, ges, geb, ins, inb, Wk, Wv);
    gstats_kernel<<<BB, 256>>>();
    q_kernel<<<BB * QQ, 64>>>(slots, qs, qb, Wq);
    for (int it = 0; it < NITER; ++it) {
        int last = (it == NITER - 1);
        if (last) attn_kernel<1><<<BB * CPB, 256, ATTN_SMEM>>>();
        else      attn_kernel<0><<<BB * CPB, 256, ATTN_SMEM>>>();
        upd_kernel<<<BB * QQ / 8, 512, UPD_SMEM>>>(Wir, Wiz, Win, bir, biz, binp,
                                                   Whr, Whz, Whn, bhn, mls, mlb,
                                                   W1, b1, W2, b2, Wq, qs, qb, out, last);
    }
}